// round 3
// baseline (speedup 1.0000x reference)
#include <cuda_runtime.h>
#include <cstdint>

#define B_  2048
#define K_  64
#define M_  64
#define D_  256
#define NI_ 15
#define MI_ 3
#define EPS_ 0.05f

// Scratch for MLP features f = concat(fq, fr) per batch: [B, 128, 256] f32 = 268 MB.
__device__ float g_f[(size_t)B_ * (K_ + M_) * D_];

// ---------------------------------------------------------------------------
// packed f32x2 helpers (FFMA2 is not generated by ptxas from C++)
// ---------------------------------------------------------------------------
__device__ __forceinline__ unsigned long long pack2(float lo, float hi) {
    unsigned long long r;
    asm("mov.b64 %0, {%1,%2};" : "=l"(r) : "f"(lo), "f"(hi));
    return r;
}
__device__ __forceinline__ void unpack2(unsigned long long v, float& lo, float& hi) {
    asm("mov.b64 {%0,%1}, %2;" : "=f"(lo), "=f"(hi) : "l"(v));
}
__device__ __forceinline__ unsigned long long fma2(unsigned long long a,
                                                   unsigned long long b,
                                                   unsigned long long c) {
    unsigned long long d;
    asm("fma.rn.f32x2 %0, %1, %2, %3;" : "=l"(d) : "l"(a), "l"(b), "l"(c));
    return d;
}

// ---------------------------------------------------------------------------
// Kernel A: fused 2-layer MLP.  f = relu(x@W1^T + b1)@W2^T + b2
// 64 rows per block, 256 threads (16x16), 4x16 register tile per thread.
// smem: xs[256][68] (input, k-major transposed), ws[32][260] (W chunk, k-major).
// ---------------------------------------------------------------------------
__global__ void __launch_bounds__(256, 2) mlp_kernel(
    const float* __restrict__ sq, const float* __restrict__ sr,
    const float* __restrict__ W1, const float* __restrict__ b1,
    const float* __restrict__ W2, const float* __restrict__ b2)
{
    extern __shared__ float sm[];
    float* xs = sm;                 // [256][68]
    float* ws = sm + 256 * 68;      // [32][260]

    const int t  = threadIdx.x;
    const int tx = t & 15;
    const int ty = t >> 4;
    const size_t g0 = (size_t)blockIdx.x * 64;   // first global row of this tile

    // Load x tile transposed: xs[d][r].  Row it: global row g0+it, d = t.
    for (int it = 0; it < 64; ++it) {
        size_t g = g0 + it;
        int b  = (int)(g >> 7);       // g / 128
        int rr = (int)(g & 127);
        float v;
        if (rr < 64) v = sq[((size_t)b * 64 + rr) * 256 + t];
        else         v = sr[((size_t)b * 64 + (rr - 64)) * 256 + t];
        xs[t * 68 + it] = v;
    }
    __syncthreads();

    unsigned long long acc[4][4][2];

    const float* Wp = W1;
    const float* bp = b1;

    for (int layer = 0; layer < 2; ++layer) {
        #pragma unroll
        for (int r = 0; r < 4; ++r)
            #pragma unroll
            for (int j = 0; j < 4; ++j) { acc[r][j][0] = 0ull; acc[r][j][1] = 0ull; }

        for (int k0 = 0; k0 < 256; k0 += 32) {
            // stage W chunk: ws[kk][e] = W[e][k0+kk]
            #pragma unroll
            for (int it = 0; it < 32; ++it) {
                int idx = t + it * 256;
                int e  = idx >> 5;
                int kk = idx & 31;
                ws[kk * 260 + e] = Wp[(size_t)e * 256 + k0 + kk];
            }
            __syncthreads();

            #pragma unroll 4
            for (int kk = 0; kk < 32; ++kk) {
                const float4 xv = *(const float4*)&xs[(k0 + kk) * 68 + 4 * ty];
                const float* wrow = &ws[kk * 260 + 4 * tx];
                ulonglong2 w0 = *(const ulonglong2*)(wrow);
                ulonglong2 w1 = *(const ulonglong2*)(wrow + 64);
                ulonglong2 w2 = *(const ulonglong2*)(wrow + 128);
                ulonglong2 w3 = *(const ulonglong2*)(wrow + 192);
                float xr[4] = {xv.x, xv.y, xv.z, xv.w};
                #pragma unroll
                for (int r = 0; r < 4; ++r) {
                    unsigned long long xp = pack2(xr[r], xr[r]);
                    acc[r][0][0] = fma2(xp, w0.x, acc[r][0][0]);
                    acc[r][0][1] = fma2(xp, w0.y, acc[r][0][1]);
                    acc[r][1][0] = fma2(xp, w1.x, acc[r][1][0]);
                    acc[r][1][1] = fma2(xp, w1.y, acc[r][1][1]);
                    acc[r][2][0] = fma2(xp, w2.x, acc[r][2][0]);
                    acc[r][2][1] = fma2(xp, w2.y, acc[r][2][1]);
                    acc[r][3][0] = fma2(xp, w3.x, acc[r][3][0]);
                    acc[r][3][1] = fma2(xp, w3.y, acc[r][3][1]);
                }
            }
            __syncthreads();
        }

        if (layer == 0) {
            // h = relu(acc + b1), write transposed back into xs (xs fully consumed)
            #pragma unroll
            for (int j = 0; j < 4; ++j) {
                #pragma unroll
                for (int p = 0; p < 2; ++p) {
                    int c = 4 * tx + 64 * j + 2 * p;
                    float blo = bp[c], bhi = bp[c + 1];
                    #pragma unroll
                    for (int r = 0; r < 4; ++r) {
                        float lo, hi;
                        unpack2(acc[r][j][p], lo, hi);
                        lo = fmaxf(lo + blo, 0.f);
                        hi = fmaxf(hi + bhi, 0.f);
                        xs[c * 68 + 4 * ty + r]       = lo;
                        xs[(c + 1) * 68 + 4 * ty + r] = hi;
                    }
                }
            }
            __syncthreads();
            Wp = W2;
            bp = b2;
        } else {
            // f = acc + b2, store to scratch (coalesced float4 per (r,j))
            #pragma unroll
            for (int r = 0; r < 4; ++r) {
                size_t row = g0 + 4 * ty + r;
                #pragma unroll
                for (int j = 0; j < 4; ++j) {
                    int c = 4 * tx + 64 * j;
                    float4 o;
                    unpack2(acc[r][j][0], o.x, o.y);
                    unpack2(acc[r][j][1], o.z, o.w);
                    o.x += bp[c];     o.y += bp[c + 1];
                    o.z += bp[c + 2]; o.w += bp[c + 3];
                    *(float4*)&g_f[row * 256 + c] = o;
                }
            }
        }
    }
}

// ---------------------------------------------------------------------------
// Kernel B: per-batch cdist + Sinkhorn + power iterations + outputs.
// One block per batch, 256 threads.
// ---------------------------------------------------------------------------
__global__ void __launch_bounds__(256, 1) sink_kernel(
    const float* __restrict__ mq, const float* __restrict__ mr,
    float* __restrict__ out)
{
    extern __shared__ float sm[];
    float* fqs = sm;                  // [256][68]
    float* frs = fqs + 256 * 68;      // [256][68]
    float* Cs  = frs + 256 * 68;      // [64][65]
    float* lKs = Cs  + 64 * 65;       // [64][65]
    float* Ts  = lKs + 64 * 65;       // [64][65]
    float* la  = Ts  + 64 * 65;
    float* lb  = la + 64;
    float* rsA = lb + 64;             // norms / rowsums
    float* rsB = rsA + 64;            // norms / colsums
    float* lmq = rsB + 64;
    float* lmr = lmq + 64;
    float* red = lmr + 64;            // [256]

    const int t  = threadIdx.x;
    const int tx = t & 15;
    const int ty = t >> 4;
    const int b  = blockIdx.x;

    float* out_sig = out;
    float* out_T   = out + B_;
    float* out_C   = out_T + (size_t)B_ * K_ * M_;
    float* out_c   = out_C + (size_t)B_ * K_ * M_;

    const float* fq = g_f + (size_t)b * 128 * 256;
    const float* fr = fq + 64 * 256;

    // Load fq/fr transposed into smem: [d][r]
    for (int it = 0; it < 64; ++it) {
        fqs[t * 68 + it] = fq[(size_t)it * 256 + t];
        frs[t * 68 + it] = fr[(size_t)it * 256 + t];
    }
    if (t < 64)       { lmq[t] = __logf(fmaxf(mq[(size_t)b * 64 + t], 1e-8f)); la[t] = 0.f; }
    else if (t < 128) { lmr[t - 64] = __logf(fmaxf(mr[(size_t)b * 64 + (t - 64)], 1e-8f)); lb[t - 64] = 0.f; }
    __syncthreads();

    // Squared norms: 2 threads per row over 128 rows
    {
        int row = t >> 1, half = t & 1;
        const float* base = (row < 64) ? fqs : frs;
        int r = row & 63;
        float s = 0.f;
        #pragma unroll 8
        for (int d = half * 128; d < half * 128 + 128; ++d) {
            float v = base[d * 68 + r];
            s += v * v;
        }
        s += __shfl_xor_sync(0xffffffffu, s, 1);
        if (half == 0) { if (row < 64) rsA[row] = s; else rsB[row - 64] = s; }
    }
    __syncthreads();

    // G = fq @ fr^T ; C = sqrt(max(nq + nr - 2G, 0)) ; lK = -C/eps + lmq + lmr
    {
        unsigned long long acc[4][2];
        #pragma unroll
        for (int r = 0; r < 4; ++r) { acc[r][0] = 0ull; acc[r][1] = 0ull; }

        #pragma unroll 4
        for (int d = 0; d < 256; ++d) {
            const float4 xv = *(const float4*)&fqs[d * 68 + 4 * ty];
            ulonglong2 yv   = *(const ulonglong2*)&frs[d * 68 + 4 * tx];
            float xr[4] = {xv.x, xv.y, xv.z, xv.w};
            #pragma unroll
            for (int r = 0; r < 4; ++r) {
                unsigned long long xp = pack2(xr[r], xr[r]);
                acc[r][0] = fma2(xp, yv.x, acc[r][0]);
                acc[r][1] = fma2(xp, yv.y, acc[r][1]);
            }
        }
        #pragma unroll
        for (int r = 0; r < 4; ++r) {
            int k = 4 * ty + r;
            float4 g4;
            unpack2(acc[r][0], g4.x, g4.y);
            unpack2(acc[r][1], g4.z, g4.w);
            float nqk = rsA[k];
            float4 c4;
            c4.x = sqrtf(fmaxf(nqk + rsB[4 * tx + 0] - 2.f * g4.x, 0.f));
            c4.y = sqrtf(fmaxf(nqk + rsB[4 * tx + 1] - 2.f * g4.y, 0.f));
            c4.z = sqrtf(fmaxf(nqk + rsB[4 * tx + 2] - 2.f * g4.z, 0.f));
            c4.w = sqrtf(fmaxf(nqk + rsB[4 * tx + 3] - 2.f * g4.w, 0.f));
            Cs[k * 65 + 4 * tx + 0] = c4.x;
            Cs[k * 65 + 4 * tx + 1] = c4.y;
            Cs[k * 65 + 4 * tx + 2] = c4.z;
            Cs[k * 65 + 4 * tx + 3] = c4.w;
            float lmqk = lmq[k];
            lKs[k * 65 + 4 * tx + 0] = -c4.x * (1.f / EPS_) + lmqk + lmr[4 * tx + 0];
            lKs[k * 65 + 4 * tx + 1] = -c4.y * (1.f / EPS_) + lmqk + lmr[4 * tx + 1];
            lKs[k * 65 + 4 * tx + 2] = -c4.z * (1.f / EPS_) + lmqk + lmr[4 * tx + 2];
            lKs[k * 65 + 4 * tx + 3] = -c4.w * (1.f / EPS_) + lmqk + lmr[4 * tx + 3];
            *(float4*)&out_C[((size_t)b * 64 + k) * 64 + 4 * tx] = c4;
        }
    }
    __syncthreads();

    // Sinkhorn: 15 iterations, log domain, 4 threads per row/col.
    const int rk = t >> 2;     // row (or col) index 0..63
    const int q  = t & 3;      // quarter
    for (int it = 0; it < NI_; ++it) {
        {   // la[k] = -lse_m(lK[k][m] + lb[m])
            float v[16], mx = -1e30f;
            #pragma unroll
            for (int j = 0; j < 16; ++j) {
                int m = q * 16 + j;
                v[j] = lKs[rk * 65 + m] + lb[m];
                mx = fmaxf(mx, v[j]);
            }
            mx = fmaxf(mx, __shfl_xor_sync(0xffffffffu, mx, 1));
            mx = fmaxf(mx, __shfl_xor_sync(0xffffffffu, mx, 2));
            float s = 0.f;
            #pragma unroll
            for (int j = 0; j < 16; ++j) s += __expf(v[j] - mx);
            s += __shfl_xor_sync(0xffffffffu, s, 1);
            s += __shfl_xor_sync(0xffffffffu, s, 2);
            if (q == 0) la[rk] = -(mx + __logf(s));
        }
        __syncthreads();
        {   // lb[m] = -lse_k(lK[k][m] + la[k])
            float v[16], mx = -1e30f;
            #pragma unroll
            for (int j = 0; j < 16; ++j) {
                int k = q * 16 + j;
                v[j] = lKs[k * 65 + rk] + la[k];
                mx = fmaxf(mx, v[j]);
            }
            mx = fmaxf(mx, __shfl_xor_sync(0xffffffffu, mx, 1));
            mx = fmaxf(mx, __shfl_xor_sync(0xffffffffu, mx, 2));
            float s = 0.f;
            #pragma unroll
            for (int j = 0; j < 16; ++j) s += __expf(v[j] - mx);
            s += __shfl_xor_sync(0xffffffffu, s, 1);
            s += __shfl_xor_sync(0xffffffffu, s, 2);
            if (q == 0) lb[rk] = -(mx + __logf(s));
        }
        __syncthreads();
    }

    // T = exp(lK + la + lb)
    {
        float lak = la[rk];
        #pragma unroll
        for (int j = 0; j < 16; ++j) {
            int m = q * 16 + j;
            Ts[rk * 65 + m] = __expf(lKs[rk * 65 + m] + lak + lb[m]);
        }
    }
    __syncthreads();

    // Power iterations: T = T*T; row-normalize; col-normalize.
    for (int it = 0; it < MI_; ++it) {
        float s = 0.f;
        #pragma unroll
        for (int j = 0; j < 16; ++j) {
            int m = q * 16 + j;
            float v = Ts[rk * 65 + m];
            v *= v;
            Ts[rk * 65 + m] = v;
            s += v;
        }
        s += __shfl_xor_sync(0xffffffffu, s, 1);
        s += __shfl_xor_sync(0xffffffffu, s, 2);
        if (q == 0) rsA[rk] = s;
        __syncthreads();
        float denom = rsA[rk] + 1e-8f;
        #pragma unroll
        for (int j = 0; j < 16; ++j) Ts[rk * 65 + q * 16 + j] /= denom;
        __syncthreads();
        float cs = 0.f;
        #pragma unroll
        for (int j = 0; j < 16; ++j) cs += Ts[(q * 16 + j) * 65 + rk];
        cs += __shfl_xor_sync(0xffffffffu, cs, 1);
        cs += __shfl_xor_sync(0xffffffffu, cs, 2);
        if (q == 0) rsB[rk] = cs;
        __syncthreads();
        #pragma unroll
        for (int j = 0; j < 16; ++j) {
            int m = q * 16 + j;
            Ts[rk * 65 + m] /= (rsB[m] + 1e-8f);
        }
        __syncthreads();
    }

    // c = sum(T*C); block reduce
    {
        float s = 0.f;
        #pragma unroll
        for (int j = 0; j < 16; ++j) {
            int m = q * 16 + j;
            s += Ts[rk * 65 + m] * Cs[rk * 65 + m];
        }
        red[t] = s;
        __syncthreads();
        for (int off = 128; off > 0; off >>= 1) {
            if (t < off) red[t] += red[t + off];
            __syncthreads();
        }
        if (t == 0) {
            float c = red[0];
            out_c[b] = c;
            out_sig[b] = 1.f / (1.f + __expf(c));
        }
    }

    // Write T (coalesced float4 per (r, tx))
    #pragma unroll
    for (int r = 0; r < 4; ++r) {
        int k = 4 * ty + r;
        float4 t4;
        t4.x = Ts[k * 65 + 4 * tx + 0];
        t4.y = Ts[k * 65 + 4 * tx + 1];
        t4.z = Ts[k * 65 + 4 * tx + 2];
        t4.w = Ts[k * 65 + 4 * tx + 3];
        *(float4*)&out_T[((size_t)b * 64 + k) * 64 + 4 * tx] = t4;
    }
}

// ---------------------------------------------------------------------------
extern "C" void kernel_launch(void* const* d_in, const int* in_sizes, int n_in,
                              void* d_out, int out_size) {
    const float* sq = (const float*)d_in[0];
    const float* sr = (const float*)d_in[1];
    const float* mq = (const float*)d_in[2];
    const float* mr = (const float*)d_in[3];
    const float* W1 = (const float*)d_in[4];
    const float* b1 = (const float*)d_in[5];
    const float* W2 = (const float*)d_in[6];
    const float* b2 = (const float*)d_in[7];
    float* out = (float*)d_out;

    const int smA = (256 * 68 + 32 * 260) * 4;                        // 102,912 B
    const int smB = (2 * 256 * 68 + 3 * 64 * 65 + 6 * 64 + 256) * 4;  // 191,744 B
    cudaFuncSetAttribute(mlp_kernel,  cudaFuncAttributeMaxDynamicSharedMemorySize, smA);
    cudaFuncSetAttribute(sink_kernel, cudaFuncAttributeMaxDynamicSharedMemorySize, smB);

    mlp_kernel<<<(B_ * (K_ + M_)) / 64, 256, smA>>>(sq, sr, W1, b1, W2, b2);
    sink_kernel<<<B_, 256, smB>>>(mq, mr, out);
}

// round 4
// speedup vs baseline: 1.1617x; 1.1617x over previous
#include <cuda_runtime.h>
#include <cstdint>

#define B_  2048
#define NI_ 15
#define MI_ 3

// ---------------------------------------------------------------------------
// packed f32x2 helpers
// ---------------------------------------------------------------------------
__device__ __forceinline__ unsigned long long pack2(float lo, float hi) {
    unsigned long long r;
    asm("mov.b64 %0, {%1,%2};" : "=l"(r) : "f"(lo), "f"(hi));
    return r;
}
__device__ __forceinline__ void unpack2(unsigned long long v, float& lo, float& hi) {
    asm("mov.b64 {%0,%1}, %2;" : "=f"(lo), "=f"(hi) : "l"(v));
}
__device__ __forceinline__ unsigned long long fma2(unsigned long long a,
                                                   unsigned long long b,
                                                   unsigned long long c) {
    unsigned long long d;
    asm("fma.rn.f32x2 %0, %1, %2, %3;" : "=l"(d) : "l"(a), "l"(b), "l"(c));
    return d;
}

// smem float offsets
#define XS_STRIDE 132
#define XS_FLOATS (256 * XS_STRIDE)              // 33792
#define WS_FLOATS (32 * 260)                     // 8320
#define WS0_OFF   XS_FLOATS
#define WS1_OFF   (XS_FLOATS + WS_FLOATS)
#define ALIAS_OFF XS_FLOATS                      // phase-2 arrays alias ws
#define SMEM_FLOATS (XS_FLOATS + 2 * WS_FLOATS)  // 50432 floats = 201728 B

// ---------------------------------------------------------------------------
// Fully fused kernel: one block per batch, 512 threads.
//   phase 1: 2-layer MLP for this batch's 128 rows (fq;fr), f kept transposed
//            in smem xs[d][row].
//   phase 2: norms, Gram, C, lK, 15 Sinkhorn iters, 3 power iters, outputs.
// ---------------------------------------------------------------------------
__global__ void __launch_bounds__(512, 1) fused_kernel(
    const float* __restrict__ sq, const float* __restrict__ sr,
    const float* __restrict__ mq, const float* __restrict__ mr,
    const float* __restrict__ W1, const float* __restrict__ b1,
    const float* __restrict__ W2, const float* __restrict__ b2,
    float* __restrict__ out)
{
    extern __shared__ float sm[];
    float* xs  = sm;                         // [256 d][132] rows 0..127
    float* ws0 = sm + WS0_OFF;
    float* ws1 = sm + WS1_OFF;

    const int t  = threadIdx.x;
    const int tx = t & 15;                   // col group (16)
    const int ty = t >> 4;                   // row group (32)
    const int b  = blockIdx.x;

    float* out_sig = out;
    float* out_T   = out + B_;
    float* out_C   = out_T + (size_t)B_ * 64 * 64;
    float* out_c   = out_C + (size_t)B_ * 64 * 64;

    // ---- load x (sq rows 0..63, sr rows 64..127) transposed into xs[d][row]
    {
        const int d    = t & 255;
        const int half = t >> 8;
        const float* src = (half ? sr : sq) + (size_t)b * 64 * 256;
        #pragma unroll 8
        for (int rr = 0; rr < 64; ++rr)
            xs[d * XS_STRIDE + half * 64 + rr] = src[rr * 256 + d];
    }
    __syncthreads();

    // ---- 2-layer MLP: out[row][e] = x[row][:] . W[e][:]  (+bias, relu on L1)
    unsigned long long acc[4][4][2];
    const float* Wp = W1;
    const float* bp = b1;

    for (int layer = 0; layer < 2; ++layer) {
        #pragma unroll
        for (int r = 0; r < 4; ++r)
            #pragma unroll
            for (int j = 0; j < 4; ++j) { acc[r][j][0] = 0ull; acc[r][j][1] = 0ull; }

        // prologue stage chunk 0 -> ws0
        #pragma unroll
        for (int i = 0; i < 16; ++i) {
            int idx = t + i * 512;
            int e  = idx >> 5;
            int kk = idx & 31;
            ws0[kk * 260 + e] = Wp[(size_t)e * 256 + kk];
        }
        __syncthreads();

        for (int c = 0; c < 8; ++c) {
            float* wcur = (c & 1) ? ws1 : ws0;
            float* wnxt = (c & 1) ? ws0 : ws1;
            if (c < 7) {
                // stage chunk c+1 early; LDG latency hidden by compute below
                #pragma unroll
                for (int i = 0; i < 16; ++i) {
                    int idx = t + i * 512;
                    int e  = idx >> 5;
                    int kk = idx & 31;
                    wnxt[kk * 260 + e] = Wp[(size_t)e * 256 + (c + 1) * 32 + kk];
                }
            }
            const int k0 = c * 32;
            #pragma unroll 4
            for (int kk = 0; kk < 32; ++kk) {
                const float4 xv = *(const float4*)&xs[(k0 + kk) * XS_STRIDE + 4 * ty];
                const float* wrow = &wcur[kk * 260 + 4 * tx];
                ulonglong2 w0 = *(const ulonglong2*)(wrow);
                ulonglong2 w1 = *(const ulonglong2*)(wrow + 64);
                ulonglong2 w2 = *(const ulonglong2*)(wrow + 128);
                ulonglong2 w3 = *(const ulonglong2*)(wrow + 192);
                float xr[4] = {xv.x, xv.y, xv.z, xv.w};
                #pragma unroll
                for (int r = 0; r < 4; ++r) {
                    unsigned long long xp = pack2(xr[r], xr[r]);
                    acc[r][0][0] = fma2(xp, w0.x, acc[r][0][0]);
                    acc[r][0][1] = fma2(xp, w0.y, acc[r][0][1]);
                    acc[r][1][0] = fma2(xp, w1.x, acc[r][1][0]);
                    acc[r][1][1] = fma2(xp, w1.y, acc[r][1][1]);
                    acc[r][2][0] = fma2(xp, w2.x, acc[r][2][0]);
                    acc[r][2][1] = fma2(xp, w2.y, acc[r][2][1]);
                    acc[r][3][0] = fma2(xp, w3.x, acc[r][3][0]);
                    acc[r][3][1] = fma2(xp, w3.y, acc[r][3][1]);
                }
            }
            __syncthreads();
        }

        // write back transposed into xs (all reads of xs/ws for this layer done)
        const bool relu = (layer == 0);
        #pragma unroll
        for (int j = 0; j < 4; ++j) {
            #pragma unroll
            for (int p = 0; p < 2; ++p) {
                int c = 4 * tx + 64 * j + 2 * p;
                float blo = bp[c], bhi = bp[c + 1];
                #pragma unroll
                for (int r = 0; r < 4; ++r) {
                    float lo, hi;
                    unpack2(acc[r][j][p], lo, hi);
                    lo += blo; hi += bhi;
                    if (relu) { lo = fmaxf(lo, 0.f); hi = fmaxf(hi, 0.f); }
                    xs[c * XS_STRIDE + 4 * ty + r]       = lo;
                    xs[(c + 1) * XS_STRIDE + 4 * ty + r] = hi;
                }
            }
        }
        __syncthreads();
        Wp = W2;
        bp = b2;
    }

    // ---- phase 2 smem (aliases ws region; ws fully consumed) ----
    float* Cs  = sm + ALIAS_OFF;             // [64][65]
    float* lKs = Cs  + 64 * 65;
    float* Ts  = lKs + 64 * 65;
    float* la  = Ts  + 64 * 65;
    float* lb  = la + 64;
    float* rsA = lb + 64;
    float* rsB = rsA + 64;
    float* lmq = rsB + 64;
    float* lmr = lmq + 64;
    float* red = lmr + 64;                   // [512]

    // norms: 4 threads per row over 128 rows
    {
        int row = t >> 2, q4 = t & 3;
        float s = 0.f;
        #pragma unroll 8
        for (int i = 0; i < 64; ++i) {
            float v = xs[(q4 * 64 + i) * XS_STRIDE + row];
            s += v * v;
        }
        s += __shfl_xor_sync(0xffffffffu, s, 1);
        s += __shfl_xor_sync(0xffffffffu, s, 2);
        if (q4 == 0) { if (row < 64) rsA[row] = s; else rsB[row - 64] = s; }
    }
    if (t < 64)       { lmq[t] = __logf(fmaxf(mq[(size_t)b * 64 + t], 1e-8f)); la[t] = 0.f; }
    else if (t < 128) { lmr[t - 64] = __logf(fmaxf(mr[(size_t)b * 64 + (t - 64)], 1e-8f)); lb[t - 64] = 0.f; }
    __syncthreads();

    // Gram: thread (gy 0..31 -> 2 k rows, gx 0..15 -> 4 m cols)
    {
        const int gx = t & 15, gy = t >> 4;
        const int k2 = 2 * gy, m4 = 4 * gx;
        unsigned long long g2[2][2];
        g2[0][0] = g2[0][1] = g2[1][0] = g2[1][1] = 0ull;
        #pragma unroll 4
        for (int d = 0; d < 256; ++d) {
            const float2 xv = *(const float2*)&xs[d * XS_STRIDE + k2];
            const ulonglong2 yv = *(const ulonglong2*)&xs[d * XS_STRIDE + 64 + m4];
            unsigned long long xp0 = pack2(xv.x, xv.x);
            unsigned long long xp1 = pack2(xv.y, xv.y);
            g2[0][0] = fma2(xp0, yv.x, g2[0][0]);
            g2[0][1] = fma2(xp0, yv.y, g2[0][1]);
            g2[1][0] = fma2(xp1, yv.x, g2[1][0]);
            g2[1][1] = fma2(xp1, yv.y, g2[1][1]);
        }
        #pragma unroll
        for (int kk = 0; kk < 2; ++kk) {
            int k = k2 + kk;
            float g[4];
            unpack2(g2[kk][0], g[0], g[1]);
            unpack2(g2[kk][1], g[2], g[3]);
            float nk = rsA[k];
            float lmqk = lmq[k];
            #pragma unroll
            for (int j = 0; j < 4; ++j) {
                int m = m4 + j;
                float cc = sqrtf(fmaxf(nk + rsB[m] - 2.f * g[j], 0.f));
                Cs[k * 65 + m]  = cc;
                lKs[k * 65 + m] = -cc * 20.0f + lmqk + lmr[m];
            }
        }
    }
    __syncthreads();

    // Sinkhorn: 15 iterations, 8 threads per row/col
    const int rk = t >> 3;
    const int q  = t & 7;
    for (int it = 0; it < NI_; ++it) {
        {   // la[k] = -lse_m(lK[k][m] + lb[m])
            float v[8], mx = -1e30f;
            #pragma unroll
            for (int j = 0; j < 8; ++j) {
                int m = q * 8 + j;
                v[j] = lKs[rk * 65 + m] + lb[m];
                mx = fmaxf(mx, v[j]);
            }
            mx = fmaxf(mx, __shfl_xor_sync(0xffffffffu, mx, 1));
            mx = fmaxf(mx, __shfl_xor_sync(0xffffffffu, mx, 2));
            mx = fmaxf(mx, __shfl_xor_sync(0xffffffffu, mx, 4));
            float s = 0.f;
            #pragma unroll
            for (int j = 0; j < 8; ++j) s += __expf(v[j] - mx);
            s += __shfl_xor_sync(0xffffffffu, s, 1);
            s += __shfl_xor_sync(0xffffffffu, s, 2);
            s += __shfl_xor_sync(0xffffffffu, s, 4);
            if (q == 0) la[rk] = -(mx + __logf(s));
        }
        __syncthreads();
        {   // lb[m] = -lse_k(lK[k][m] + la[k])
            float v[8], mx = -1e30f;
            #pragma unroll
            for (int j = 0; j < 8; ++j) {
                int k = q * 8 + j;
                v[j] = lKs[k * 65 + rk] + la[k];
                mx = fmaxf(mx, v[j]);
            }
            mx = fmaxf(mx, __shfl_xor_sync(0xffffffffu, mx, 1));
            mx = fmaxf(mx, __shfl_xor_sync(0xffffffffu, mx, 2));
            mx = fmaxf(mx, __shfl_xor_sync(0xffffffffu, mx, 4));
            float s = 0.f;
            #pragma unroll
            for (int j = 0; j < 8; ++j) s += __expf(v[j] - mx);
            s += __shfl_xor_sync(0xffffffffu, s, 1);
            s += __shfl_xor_sync(0xffffffffu, s, 2);
            s += __shfl_xor_sync(0xffffffffu, s, 4);
            if (q == 0) lb[rk] = -(mx + __logf(s));
        }
        __syncthreads();
    }

    // T = exp(lK + la + lb)
    {
        float lak = la[rk];
        #pragma unroll
        for (int j = 0; j < 8; ++j) {
            int m = q * 8 + j;
            Ts[rk * 65 + m] = __expf(lKs[rk * 65 + m] + lak + lb[m]);
        }
    }
    __syncthreads();

    // Power iterations
    for (int it = 0; it < MI_; ++it) {
        float s = 0.f;
        #pragma unroll
        for (int j = 0; j < 8; ++j) {
            int m = q * 8 + j;
            float v = Ts[rk * 65 + m];
            v *= v;
            Ts[rk * 65 + m] = v;
            s += v;
        }
        s += __shfl_xor_sync(0xffffffffu, s, 1);
        s += __shfl_xor_sync(0xffffffffu, s, 2);
        s += __shfl_xor_sync(0xffffffffu, s, 4);
        if (q == 0) rsA[rk] = s;
        __syncthreads();
        float denom = 1.f / (rsA[rk] + 1e-8f);
        #pragma unroll
        for (int j = 0; j < 8; ++j) Ts[rk * 65 + q * 8 + j] *= denom;
        __syncthreads();
        float cs = 0.f;
        #pragma unroll
        for (int j = 0; j < 8; ++j) cs += Ts[(q * 8 + j) * 65 + rk];
        cs += __shfl_xor_sync(0xffffffffu, cs, 1);
        cs += __shfl_xor_sync(0xffffffffu, cs, 2);
        cs += __shfl_xor_sync(0xffffffffu, cs, 4);
        if (q == 0) rsB[rk] = cs;
        __syncthreads();
        #pragma unroll
        for (int j = 0; j < 8; ++j) {
            int m = q * 8 + j;
            Ts[rk * 65 + m] /= (rsB[m] + 1e-8f);
        }
        __syncthreads();
    }

    // c = sum(T*C)
    {
        float s = 0.f;
        #pragma unroll
        for (int j = 0; j < 8; ++j) {
            int m = q * 8 + j;
            s += Ts[rk * 65 + m] * Cs[rk * 65 + m];
        }
        red[t] = s;
        __syncthreads();
        for (int off = 256; off > 0; off >>= 1) {
            if (t < off) red[t] += red[t + off];
            __syncthreads();
        }
        if (t == 0) {
            float c = red[0];
            out_c[b] = c;
            out_sig[b] = 1.f / (1.f + __expf(c));
        }
    }

    // write T and C: thread -> row t>>3, cols (t&7)*8 .. +7
    {
        int row = t >> 3;
        int cb  = (t & 7) * 8;
        float4 a4, b4;
        a4.x = Ts[row * 65 + cb + 0]; a4.y = Ts[row * 65 + cb + 1];
        a4.z = Ts[row * 65 + cb + 2]; a4.w = Ts[row * 65 + cb + 3];
        b4.x = Ts[row * 65 + cb + 4]; b4.y = Ts[row * 65 + cb + 5];
        b4.z = Ts[row * 65 + cb + 6]; b4.w = Ts[row * 65 + cb + 7];
        *(float4*)&out_T[((size_t)b * 64 + row) * 64 + cb]     = a4;
        *(float4*)&out_T[((size_t)b * 64 + row) * 64 + cb + 4] = b4;
        a4.x = Cs[row * 65 + cb + 0]; a4.y = Cs[row * 65 + cb + 1];
        a4.z = Cs[row * 65 + cb + 2]; a4.w = Cs[row * 65 + cb + 3];
        b4.x = Cs[row * 65 + cb + 4]; b4.y = Cs[row * 65 + cb + 5];
        b4.z = Cs[row * 65 + cb + 6]; b4.w = Cs[row * 65 + cb + 7];
        *(float4*)&out_C[((size_t)b * 64 + row) * 64 + cb]     = a4;
        *(float4*)&out_C[((size_t)b * 64 + row) * 64 + cb + 4] = b4;
    }
}

// ---------------------------------------------------------------------------
extern "C" void kernel_launch(void* const* d_in, const int* in_sizes, int n_in,
                              void* d_out, int out_size) {
    const float* sq = (const float*)d_in[0];
    const float* sr = (const float*)d_in[1];
    const float* mq = (const float*)d_in[2];
    const float* mr = (const float*)d_in[3];
    const float* W1 = (const float*)d_in[4];
    const float* b1 = (const float*)d_in[5];
    const float* W2 = (const float*)d_in[6];
    const float* b2 = (const float*)d_in[7];
    float* out = (float*)d_out;

    const int smem = SMEM_FLOATS * 4;   // 201728 B
    cudaFuncSetAttribute(fused_kernel, cudaFuncAttributeMaxDynamicSharedMemorySize, smem);
    fused_kernel<<<B_, 512, smem>>>(sq, sr, mq, mr, W1, b1, W2, b2, out);
}

// round 7
// speedup vs baseline: 1.1863x; 1.0211x over previous
#include <cuda_runtime.h>
#include <cstdint>

#define B_  2048
#define NI_ 15
#define MI_ 3

// ---------------------------------------------------------------------------
// smem layout (bytes):
//   xbuf/fs region [0, 135168): phase1a x row-major [128][264] f32 (135168B max),
//     then h row-major [128][264], then f transposed fs[256 d][132 row] f32.
//   ws [135168, 201728): 2 x 32x260 f32 W chunk buffers (phase 2 aliases:
//     Cs@135168, lKs@151808, Ts@168448, each 64x65 f32)
//   small arrays [201728, 207360)
// ---------------------------------------------------------------------------
#define XROW_STRIDE 264
#define FS_STRIDE   132
#define WS0_OFF_F   (135168 / 4)
#define WS1_OFF_F   (168448 / 4)
#define CS_OFF_F    (135168 / 4)
#define LKS_OFF_F   (151808 / 4)
#define TS_OFF_F    (168448 / 4)
#define B1S_OFF_F   (201728 / 4)
#define B2S_OFF_F   (202752 / 4)
#define LA_OFF_F    (203776 / 4)
#define LB_OFF_F    (204032 / 4)
#define RSA_OFF_F   (204288 / 4)
#define RSB_OFF_F   (204544 / 4)
#define LMQ_OFF_F   (204800 / 4)
#define LMR_OFF_F   (205056 / 4)
#define RED_OFF_F   (205312 / 4)
#define SMEM_BYTES  207360

// W pre-transposed k-major: g_Wt[layer][k][e], 512 KB (L2-resident).
__device__ float g_Wt[2 * 256 * 256];

// ---------------------------------------------------------------------------
// packed f32x2 helpers (ptxas never auto-generates FFMA2 from C++)
// ---------------------------------------------------------------------------
__device__ __forceinline__ unsigned long long pack2(float lo, float hi) {
    unsigned long long r;
    asm("mov.b64 %0, {%1,%2};" : "=l"(r) : "f"(lo), "f"(hi));
    return r;
}
__device__ __forceinline__ void unpack2(unsigned long long v, float& lo, float& hi) {
    asm("mov.b64 {%0,%1}, %2;" : "=f"(lo), "=f"(hi) : "l"(v));
}
__device__ __forceinline__ unsigned long long fma2(unsigned long long a,
                                                   unsigned long long b,
                                                   unsigned long long c) {
    unsigned long long d;
    asm("fma.rn.f32x2 %0, %1, %2, %3;" : "=l"(d) : "l"(a), "l"(b), "l"(c));
    return d;
}

// ---------------------------------------------------------------------------
// W transpose prep: g_Wt[L][k][e] = W_L[e][k]
// ---------------------------------------------------------------------------
__global__ void wprep_kernel(const float* __restrict__ W1, const float* __restrict__ W2) {
    for (int i = blockIdx.x * 256 + threadIdx.x; i < 131072; i += gridDim.x * 256) {
        int L = i >> 16;
        int r = i & 65535;
        int k = r >> 8;
        int e = r & 255;
        g_Wt[i] = (L ? W2 : W1)[(size_t)e * 256 + k];
    }
}

// ---------------------------------------------------------------------------
// Fused kernel: one block per batch, 512 threads.
// ---------------------------------------------------------------------------
__global__ void __launch_bounds__(512, 1) fused_kernel(
    const float* __restrict__ sq, const float* __restrict__ sr,
    const float* __restrict__ mq, const float* __restrict__ mr,
    const float* __restrict__ b1, const float* __restrict__ b2,
    float* __restrict__ out)
{
    extern __shared__ float sm[];
    float* xbuf = sm;                    // row-major [128][264] (x, then h)
    float* fs   = sm;                    // transposed f [256][132] (after layer 2)
    float* ws0  = sm + WS0_OFF_F;
    float* ws1  = sm + WS1_OFF_F;
    float* b1s  = sm + B1S_OFF_F;
    float* b2s  = sm + B2S_OFF_F;
    float* la   = sm + LA_OFF_F;
    float* lb   = sm + LB_OFF_F;
    float* rsA  = sm + RSA_OFF_F;
    float* rsB  = sm + RSB_OFF_F;
    float* lmq  = sm + LMQ_OFF_F;
    float* lmr  = sm + LMR_OFF_F;
    float* red  = sm + RED_OFF_F;
    float* Cs   = sm + CS_OFF_F;
    float* lKs  = sm + LKS_OFF_F;
    float* Ts   = sm + TS_OFF_F;

    const int t  = threadIdx.x;
    const int tx = t & 31;               // col group (8 cols each)
    const int ty = t >> 5;               // row group (8 rows each)
    const int b  = blockIdx.x;

    float* out_sig = out;
    float* out_T   = out + B_;
    float* out_C   = out_T + (size_t)B_ * 64 * 64;
    float* out_c   = out_C + (size_t)B_ * 64 * 64;

    // ---- load x row-major (straight coalesced float4 copy) ------------------
    {
        #pragma unroll
        for (int i = 0; i < 16; ++i) {
            int idx = t + i * 512;           // float4 index, 8192 total
            int row = idx >> 6;
            int d4  = (idx & 63) << 2;
            const float* src = (row < 64)
                ? sq + ((size_t)b * 64 + row) * 256
                : sr + ((size_t)b * 64 + (row - 64)) * 256;
            *(float4*)&xbuf[row * XROW_STRIDE + d4] = *(const float4*)(src + d4);
        }
        if (t < 256) b1s[t] = b1[t];
        else         b2s[t - 256] = b2[t - 256];
    }
    __syncthreads();

    // ---- 2-layer MLP, 8x8 tile per thread -----------------------------------
    unsigned long long acc[8][4];

    for (int layer = 0; layer < 2; ++layer) {
        const float* Wt = g_Wt + layer * 65536;
        const float* bp = layer ? b2s : b1s;

        #pragma unroll
        for (int r = 0; r < 8; ++r)
            #pragma unroll
            for (int j = 0; j < 4; ++j) acc[r][j] = 0ull;

        // stage chunk 0 -> ws0 (coalesced LDG.128 + conflict-free STS.128)
        #pragma unroll
        for (int i = 0; i < 4; ++i) {
            int idx = t + i * 512;
            int kk = idx >> 6, e4 = (idx & 63) << 2;
            *(float4*)&ws0[kk * 260 + e4] = *(const float4*)&Wt[kk * 256 + e4];
        }
        __syncthreads();

        for (int c = 0; c < 8; ++c) {
            float* wcur = (c & 1) ? ws1 : ws0;
            float* wnxt = (c & 1) ? ws0 : ws1;
            if (c < 7) {
                #pragma unroll
                for (int i = 0; i < 4; ++i) {
                    int idx = t + i * 512;
                    int kk = idx >> 6, e4 = (idx & 63) << 2;
                    *(float4*)&wnxt[kk * 260 + e4] =
                        *(const float4*)&Wt[(c + 1) * 8192 + kk * 256 + e4];
                }
            }
            const int k0 = c * 32;
            #pragma unroll
            for (int kb = 0; kb < 16; ++kb) {          // 2 k per block
                float2 xq[8];
                #pragma unroll
                for (int r = 0; r < 8; ++r)
                    xq[r] = *(const float2*)&xbuf[(8 * ty + r) * XROW_STRIDE + k0 + 2 * kb];
                #pragma unroll
                for (int k2 = 0; k2 < 2; ++k2) {
                    const float* wrow = &wcur[(2 * kb + k2) * 260 + 8 * tx];
                    ulonglong2 w0 = *(const ulonglong2*)(wrow);
                    ulonglong2 w1 = *(const ulonglong2*)(wrow + 4);
                    #pragma unroll
                    for (int r = 0; r < 8; ++r) {
                        float xv = k2 ? xq[r].y : xq[r].x;
                        unsigned long long xp = pack2(xv, xv);
                        acc[r][0] = fma2(xp, w0.x, acc[r][0]);
                        acc[r][1] = fma2(xp, w0.y, acc[r][1]);
                        acc[r][2] = fma2(xp, w1.x, acc[r][2]);
                        acc[r][3] = fma2(xp, w1.y, acc[r][3]);
                    }
                }
            }
            __syncthreads();
        }

        if (layer == 0) {
            // h = relu(acc + b1) -> row-major back into xbuf (x fully consumed)
            float blo[8];
            #pragma unroll
            for (int j = 0; j < 8; ++j) blo[j] = bp[8 * tx + j];
            #pragma unroll
            for (int r = 0; r < 8; ++r) {
                float v[8];
                #pragma unroll
                for (int p = 0; p < 4; ++p) unpack2(acc[r][p], v[2 * p], v[2 * p + 1]);
                float4 q0, q1;
                q0.x = fmaxf(v[0] + blo[0], 0.f); q0.y = fmaxf(v[1] + blo[1], 0.f);
                q0.z = fmaxf(v[2] + blo[2], 0.f); q0.w = fmaxf(v[3] + blo[3], 0.f);
                q1.x = fmaxf(v[4] + blo[4], 0.f); q1.y = fmaxf(v[5] + blo[5], 0.f);
                q1.z = fmaxf(v[6] + blo[6], 0.f); q1.w = fmaxf(v[7] + blo[7], 0.f);
                *(float4*)&xbuf[(8 * ty + r) * XROW_STRIDE + 8 * tx]     = q0;
                *(float4*)&xbuf[(8 * ty + r) * XROW_STRIDE + 8 * tx + 4] = q1;
            }
            __syncthreads();
        } else {
            // f = acc + b2 -> transposed fs[d][row], norms from registers
            float nrm[8];
            #pragma unroll
            for (int r = 0; r < 8; ++r) nrm[r] = 0.f;
            #pragma unroll
            for (int j = 0; j < 8; ++j) {
                int cidx = 8 * tx + j;
                float bias = bp[cidx];
                float v[8];
                #pragma unroll
                for (int r = 0; r < 8; ++r) {
                    float lo, hi;
                    unpack2(acc[r][j >> 1], lo, hi);
                    float f = ((j & 1) ? hi : lo) + bias;
                    v[r] = f;
                    nrm[r] += f * f;
                }
                *(float4*)&fs[cidx * FS_STRIDE + 8 * ty]     = make_float4(v[0], v[1], v[2], v[3]);
                *(float4*)&fs[cidx * FS_STRIDE + 8 * ty + 4] = make_float4(v[4], v[5], v[6], v[7]);
            }
            #pragma unroll
            for (int o = 16; o > 0; o >>= 1)
                #pragma unroll
                for (int r = 0; r < 8; ++r)
                    nrm[r] += __shfl_xor_sync(0xffffffffu, nrm[r], o);
            if ((t & 31) == 0) {
                #pragma unroll
                for (int r = 0; r < 8; ++r) {
                    int row = 8 * ty + r;
                    if (row < 64) rsA[row] = nrm[r];
                    else          rsB[row - 64] = nrm[r];
                }
            }
        }
    }

    if (t < 64)       { lmq[t] = __logf(fmaxf(mq[(size_t)b * 64 + t], 1e-8f)); la[t] = 0.f; }
    else if (t < 128) { lmr[t - 64] = __logf(fmaxf(mr[(size_t)b * 64 + (t - 64)], 1e-8f)); lb[t - 64] = 0.f; }
    __syncthreads();

    // ---- Gram -> C, lK (reads transposed fs) --------------------------------
    {
        const int gx = t & 15, gy = t >> 4;
        const int k2 = 2 * gy, m4 = 4 * gx;
        unsigned long long g2[2][2];
        g2[0][0] = g2[0][1] = g2[1][0] = g2[1][1] = 0ull;
        #pragma unroll 4
        for (int d = 0; d < 256; ++d) {
            const float2 xv = *(const float2*)&fs[d * FS_STRIDE + k2];
            const ulonglong2 yv = *(const ulonglong2*)&fs[d * FS_STRIDE + 64 + m4];
            unsigned long long xp0 = pack2(xv.x, xv.x);
            unsigned long long xp1 = pack2(xv.y, xv.y);
            g2[0][0] = fma2(xp0, yv.x, g2[0][0]);
            g2[0][1] = fma2(xp0, yv.y, g2[0][1]);
            g2[1][0] = fma2(xp1, yv.x, g2[1][0]);
            g2[1][1] = fma2(xp1, yv.y, g2[1][1]);
        }
        #pragma unroll
        for (int kk = 0; kk < 2; ++kk) {
            int k = k2 + kk;
            float g[4];
            unpack2(g2[kk][0], g[0], g[1]);
            unpack2(g2[kk][1], g[2], g[3]);
            float nk = rsA[k];
            float lmqk = lmq[k];
            #pragma unroll
            for (int j = 0; j < 4; ++j) {
                int m = m4 + j;
                float cc = sqrtf(fmaxf(nk + rsB[m] - 2.f * g[j], 0.f));
                Cs[k * 65 + m]  = cc;
                lKs[k * 65 + m] = -cc * 20.0f + lmqk + lmr[m];
            }
        }
    }
    __syncthreads();

    // ---- Sinkhorn: 15 iterations, 8 threads per row/col ---------------------
    const int rk = t >> 3;
    const int q  = t & 7;
    for (int it = 0; it < NI_; ++it) {
        {
            float v[8], mx = -1e30f;
            #pragma unroll
            for (int j = 0; j < 8; ++j) {
                int m = q * 8 + j;
                v[j] = lKs[rk * 65 + m] + lb[m];
                mx = fmaxf(mx, v[j]);
            }
            mx = fmaxf(mx, __shfl_xor_sync(0xffffffffu, mx, 1));
            mx = fmaxf(mx, __shfl_xor_sync(0xffffffffu, mx, 2));
            mx = fmaxf(mx, __shfl_xor_sync(0xffffffffu, mx, 4));
            float s = 0.f;
            #pragma unroll
            for (int j = 0; j < 8; ++j) s += __expf(v[j] - mx);
            s += __shfl_xor_sync(0xffffffffu, s, 1);
            s += __shfl_xor_sync(0xffffffffu, s, 2);
            s += __shfl_xor_sync(0xffffffffu, s, 4);
            if (q == 0) la[rk] = -(mx + __logf(s));
        }
        __syncthreads();
        {
            float v[8], mx = -1e30f;
            #pragma unroll
            for (int j = 0; j < 8; ++j) {
                int k = q * 8 + j;
                v[j] = lKs[k * 65 + rk] + la[k];
                mx = fmaxf(mx, v[j]);
            }
            mx = fmaxf(mx, __shfl_xor_sync(0xffffffffu, mx, 1));
            mx = fmaxf(mx, __shfl_xor_sync(0xffffffffu, mx, 2));
            mx = fmaxf(mx, __shfl_xor_sync(0xffffffffu, mx, 4));
            float s = 0.f;
            #pragma unroll
            for (int j = 0; j < 8; ++j) s += __expf(v[j] - mx);
            s += __shfl_xor_sync(0xffffffffu, s, 1);
            s += __shfl_xor_sync(0xffffffffu, s, 2);
            s += __shfl_xor_sync(0xffffffffu, s, 4);
            if (q == 0) lb[rk] = -(mx + __logf(s));
        }
        __syncthreads();
    }

    // ---- T = exp(lK + la + lb) ---------------------------------------------
    {
        float lak = la[rk];
        #pragma unroll
        for (int j = 0; j < 8; ++j) {
            int m = q * 8 + j;
            Ts[rk * 65 + m] = __expf(lKs[rk * 65 + m] + lak + lb[m]);
        }
    }
    __syncthreads();

    // ---- power iterations ---------------------------------------------------
    for (int it = 0; it < MI_; ++it) {
        float s = 0.f;
        #pragma unroll
        for (int j = 0; j < 8; ++j) {
            int m = q * 8 + j;
            float v = Ts[rk * 65 + m];
            v *= v;
            Ts[rk * 65 + m] = v;
            s += v;
        }
        s += __shfl_xor_sync(0xffffffffu, s, 1);
        s += __shfl_xor_sync(0xffffffffu, s, 2);
        s += __shfl_xor_sync(0xffffffffu, s, 4);
        if (q == 0) rsA[rk] = s;
        __syncthreads();
        float dn = 1.f / (rsA[rk] + 1e-8f);
        #pragma unroll
        for (int j = 0; j < 8; ++j) Ts[rk * 65 + q * 8 + j] *= dn;
        __syncthreads();
        float cs = 0.f;
        #pragma unroll
        for (int j = 0; j < 8; ++j) cs += Ts[(q * 8 + j) * 65 + rk];
        cs += __shfl_xor_sync(0xffffffffu, cs, 1);
        cs += __shfl_xor_sync(0xffffffffu, cs, 2);
        cs += __shfl_xor_sync(0xffffffffu, cs, 4);
        if (q == 0) rsB[rk] = cs;
        __syncthreads();
        #pragma unroll
        for (int j = 0; j < 8; ++j) {
            int m = q * 8 + j;
            Ts[rk * 65 + m] /= (rsB[m] + 1e-8f);
        }
        __syncthreads();
    }

    // ---- c, sigmoid ---------------------------------------------------------
    {
        float s = 0.f;
        #pragma unroll
        for (int j = 0; j < 8; ++j) {
            int m = q * 8 + j;
            s += Ts[rk * 65 + m] * Cs[rk * 65 + m];
        }
        red[t] = s;
        __syncthreads();
        for (int off = 256; off > 0; off >>= 1) {
            if (t < off) red[t] += red[t + off];
            __syncthreads();
        }
        if (t == 0) {
            float c = red[0];
            out_c[b] = c;
            out_sig[b] = 1.f / (1.f + __expf(c));
        }
    }

    // ---- write T, C ---------------------------------------------------------
    {
        int row = t >> 3;
        int cb  = (t & 7) * 8;
        float4 a4, b4;
        a4.x = Ts[row * 65 + cb + 0]; a4.y = Ts[row * 65 + cb + 1];
        a4.z = Ts[row * 65 + cb + 2]; a4.w = Ts[row * 65 + cb + 3];
        b4.x = Ts[row * 65 + cb + 4]; b4.y = Ts[row * 65 + cb + 5];
        b4.z = Ts[row * 65 + cb + 6]; b4.w = Ts[row * 65 + cb + 7];
        *(float4*)&out_T[((size_t)b * 64 + row) * 64 + cb]     = a4;
        *(float4*)&out_T[((size_t)b * 64 + row) * 64 + cb + 4] = b4;
        a4.x = Cs[row * 65 + cb + 0]; a4.y = Cs[row * 65 + cb + 1];
        a4.z = Cs[row * 65 + cb + 2]; a4.w = Cs[row * 65 + cb + 3];
        b4.x = Cs[row * 65 + cb + 4]; b4.y = Cs[row * 65 + cb + 5];
        b4.z = Cs[row * 65 + cb + 6]; b4.w = Cs[row * 65 + cb + 7];
        *(float4*)&out_C[((size_t)b * 64 + row) * 64 + cb]     = a4;
        *(float4*)&out_C[((size_t)b * 64 + row) * 64 + cb + 4] = b4;
    }
}

// ---------------------------------------------------------------------------
extern "C" void kernel_launch(void* const* d_in, const int* in_sizes, int n_in,
                              void* d_out, int out_size) {
    const float* sq = (const float*)d_in[0];
    const float* sr = (const float*)d_in[1];
    const float* mq = (const float*)d_in[2];
    const float* mr = (const float*)d_in[3];
    const float* W1 = (const float*)d_in[4];
    const float* b1 = (const float*)d_in[5];
    const float* W2 = (const float*)d_in[6];
    const float* b2 = (const float*)d_in[7];
    float* out = (float*)d_out;

    cudaFuncSetAttribute(fused_kernel, cudaFuncAttributeMaxDynamicSharedMemorySize, SMEM_BYTES);

    wprep_kernel<<<64, 256>>>(W1, W2);
    fused_kernel<<<B_, 512, SMEM_BYTES>>>(sq, sr, mq, mr, b1, b2, out);
}

// round 8
// speedup vs baseline: 1.2460x; 1.0504x over previous
#include <cuda_runtime.h>
#include <cstdint>

#define B_  2048
#define NI_ 15
#define MI_ 3

// ---------------------------------------------------------------------------
// smem layout (bytes):
//   [0, 135168): phase1 x/h row-major [128][264] f32; after layer 2 this
//     region becomes fs = f transposed [256 d][132 row] f32.
//   [135168, 201728): 2 x (32k x 260e) f32 W chunk buffers.
//     phase 2 aliases: Cs@135168, lKs@151808, Ts@168448 (each 64x65 f32)
//   [201728, 207360): biases + small arrays
// ---------------------------------------------------------------------------
#define XROW_STRIDE 264
#define FS_STRIDE   132
#define WS0_OFF_F   (135168 / 4)
#define WS1_OFF_F   (168448 / 4)
#define CS_OFF_F    (135168 / 4)
#define LKS_OFF_F   (151808 / 4)
#define TS_OFF_F    (168448 / 4)
#define B1S_OFF_F   (201728 / 4)
#define B2S_OFF_F   (202752 / 4)
#define LA_OFF_F    (203776 / 4)
#define LB_OFF_F    (204032 / 4)
#define RSA_OFF_F   (204288 / 4)
#define RSB_OFF_F   (204544 / 4)
#define LMQ_OFF_F   (204800 / 4)
#define LMR_OFF_F   (205056 / 4)
#define RED_OFF_F   (205312 / 4)
#define SMEM_BYTES  207360

// W pre-transposed k-major: g_Wt[layer][k][e], 512 KB (L2-resident).
__device__ float g_Wt[2 * 256 * 256];

// ---------------------------------------------------------------------------
// packed f32x2 helpers (ptxas never auto-generates FFMA2 from C++)
// ---------------------------------------------------------------------------
__device__ __forceinline__ unsigned long long pack2(float lo, float hi) {
    unsigned long long r;
    asm("mov.b64 %0, {%1,%2};" : "=l"(r) : "f"(lo), "f"(hi));
    return r;
}
__device__ __forceinline__ void unpack2(unsigned long long v, float& lo, float& hi) {
    asm("mov.b64 {%0,%1}, %2;" : "=f"(lo), "=f"(hi) : "l"(v));
}
__device__ __forceinline__ unsigned long long fma2(unsigned long long a,
                                                   unsigned long long b,
                                                   unsigned long long c) {
    unsigned long long d;
    asm("fma.rn.f32x2 %0, %1, %2, %3;" : "=l"(d) : "l"(a), "l"(b), "l"(c));
    return d;
}

// ---------------------------------------------------------------------------
// W transpose prep: g_Wt[L][k][e] = W_L[e][k]
// ---------------------------------------------------------------------------
__global__ void wprep_kernel(const float* __restrict__ W1, const float* __restrict__ W2) {
    for (int i = blockIdx.x * 256 + threadIdx.x; i < 131072; i += gridDim.x * 256) {
        int L = i >> 16;
        int r = i & 65535;
        int k = r >> 8;
        int e = r & 255;
        g_Wt[i] = (L ? W2 : W1)[(size_t)e * 256 + k];
    }
}

// ---------------------------------------------------------------------------
// Fused kernel: one block per batch, 256 threads, 16x8 tile per thread.
// ---------------------------------------------------------------------------
__global__ void __launch_bounds__(256, 1) fused_kernel(
    const float* __restrict__ sq, const float* __restrict__ sr,
    const float* __restrict__ mq, const float* __restrict__ mr,
    const float* __restrict__ b1, const float* __restrict__ b2,
    float* __restrict__ out)
{
    extern __shared__ float sm[];
    float* xbuf = sm;                    // row-major [128][264] (x, then h)
    float* fs   = sm;                    // transposed f [256][132] (after layer 2)
    float* ws0  = sm + WS0_OFF_F;
    float* ws1  = sm + WS1_OFF_F;
    float* b1s  = sm + B1S_OFF_F;
    float* b2s  = sm + B2S_OFF_F;
    float* la   = sm + LA_OFF_F;
    float* lb   = sm + LB_OFF_F;
    float* rsA  = sm + RSA_OFF_F;
    float* rsB  = sm + RSB_OFF_F;
    float* lmq  = sm + LMQ_OFF_F;
    float* lmr  = sm + LMR_OFF_F;
    float* red  = sm + RED_OFF_F;
    float* Cs   = sm + CS_OFF_F;
    float* lKs  = sm + LKS_OFF_F;
    float* Ts   = sm + TS_OFF_F;

    const int t  = threadIdx.x;
    const int tx = t & 31;               // col group: cols 8*tx .. 8*tx+7
    const int ty = t >> 5;               // row group: rows 16*ty .. 16*ty+15 (warp-uniform)
    const int b  = blockIdx.x;

    float* out_sig = out;
    float* out_T   = out + B_;
    float* out_C   = out_T + (size_t)B_ * 64 * 64;
    float* out_c   = out_C + (size_t)B_ * 64 * 64;

    // ---- load x row-major (coalesced float4 copy) ---------------------------
    {
        #pragma unroll
        for (int i = 0; i < 32; ++i) {
            int idx = t + i * 256;           // float4 index, 8192 total
            int row = idx >> 6;
            int d4  = (idx & 63) << 2;
            const float* src = (row < 64)
                ? sq + ((size_t)b * 64 + row) * 256
                : sr + ((size_t)b * 64 + (row - 64)) * 256;
            *(float4*)&xbuf[row * XROW_STRIDE + d4] = *(const float4*)(src + d4);
        }
        b1s[t] = b1[t];
        b2s[t] = b2[t];
    }
    __syncthreads();

    // ---- 2-layer MLP, 16x8 tile per thread ----------------------------------
    unsigned long long acc[16][4];

    for (int layer = 0; layer < 2; ++layer) {
        const float* Wt = g_Wt + layer * 65536;
        const float* bp = layer ? b2s : b1s;

        #pragma unroll
        for (int r = 0; r < 16; ++r)
            #pragma unroll
            for (int j = 0; j < 4; ++j) acc[r][j] = 0ull;

        // stage chunk 0 -> ws0 (coalesced LDG.128 + conflict-free STS.128)
        #pragma unroll
        for (int i = 0; i < 8; ++i) {
            int idx = t + i * 256;
            int kk = idx >> 6, e4 = (idx & 63) << 2;
            *(float4*)&ws0[kk * 260 + e4] = *(const float4*)&Wt[kk * 256 + e4];
        }
        __syncthreads();

        for (int c = 0; c < 8; ++c) {
            float* wcur = (c & 1) ? ws1 : ws0;
            float* wnxt = (c & 1) ? ws0 : ws1;
            if (c < 7) {
                #pragma unroll
                for (int i = 0; i < 8; ++i) {
                    int idx = t + i * 256;
                    int kk = idx >> 6, e4 = (idx & 63) << 2;
                    *(float4*)&wnxt[kk * 260 + e4] =
                        *(const float4*)&Wt[(c + 1) * 8192 + kk * 256 + e4];
                }
            }
            const int k0 = c * 32;
            #pragma unroll
            for (int kb = 0; kb < 16; ++kb) {          // 2 k per block
                float2 xq[16];
                #pragma unroll
                for (int r = 0; r < 16; ++r)
                    xq[r] = *(const float2*)&xbuf[(16 * ty + r) * XROW_STRIDE + k0 + 2 * kb];
                #pragma unroll
                for (int k2 = 0; k2 < 2; ++k2) {
                    const float* wrow = &wcur[(2 * kb + k2) * 260 + 8 * tx];
                    ulonglong2 w0 = *(const ulonglong2*)(wrow);
                    ulonglong2 w1 = *(const ulonglong2*)(wrow + 4);
                    #pragma unroll
                    for (int r = 0; r < 16; ++r) {
                        float xv = k2 ? xq[r].y : xq[r].x;
                        unsigned long long xp = pack2(xv, xv);
                        acc[r][0] = fma2(xp, w0.x, acc[r][0]);
                        acc[r][1] = fma2(xp, w0.y, acc[r][1]);
                        acc[r][2] = fma2(xp, w1.x, acc[r][2]);
                        acc[r][3] = fma2(xp, w1.y, acc[r][3]);
                    }
                }
            }
            __syncthreads();
        }

        if (layer == 0) {
            // h = relu(acc + b1) -> row-major back into xbuf (x fully consumed)
            float bb[8];
            #pragma unroll
            for (int j = 0; j < 8; ++j) bb[j] = bp[8 * tx + j];
            #pragma unroll
            for (int r = 0; r < 16; ++r) {
                float v[8];
                #pragma unroll
                for (int p = 0; p < 4; ++p) unpack2(acc[r][p], v[2 * p], v[2 * p + 1]);
                float4 q0, q1;
                q0.x = fmaxf(v[0] + bb[0], 0.f); q0.y = fmaxf(v[1] + bb[1], 0.f);
                q0.z = fmaxf(v[2] + bb[2], 0.f); q0.w = fmaxf(v[3] + bb[3], 0.f);
                q1.x = fmaxf(v[4] + bb[4], 0.f); q1.y = fmaxf(v[5] + bb[5], 0.f);
                q1.z = fmaxf(v[6] + bb[6], 0.f); q1.w = fmaxf(v[7] + bb[7], 0.f);
                *(float4*)&xbuf[(16 * ty + r) * XROW_STRIDE + 8 * tx]     = q0;
                *(float4*)&xbuf[(16 * ty + r) * XROW_STRIDE + 8 * tx + 4] = q1;
            }
            __syncthreads();
        } else {
            // f = acc + b2 -> transposed fs[d][row], norms from registers
            float nrm[16];
            #pragma unroll
            for (int r = 0; r < 16; ++r) nrm[r] = 0.f;
            #pragma unroll
            for (int j = 0; j < 8; ++j) {
                int cidx = 8 * tx + j;
                float bias = bp[cidx];
                float v[16];
                #pragma unroll
                for (int r = 0; r < 16; ++r) {
                    float lo, hi;
                    unpack2(acc[r][j >> 1], lo, hi);
                    float f = ((j & 1) ? hi : lo) + bias;
                    v[r] = f;
                    nrm[r] += f * f;
                }
                #pragma unroll
                for (int p = 0; p < 4; ++p)
                    *(float4*)&fs[cidx * FS_STRIDE + 16 * ty + 4 * p] =
                        make_float4(v[4 * p], v[4 * p + 1], v[4 * p + 2], v[4 * p + 3]);
            }
            #pragma unroll
            for (int o = 16; o > 0; o >>= 1)
                #pragma unroll
                for (int r = 0; r < 16; ++r)
                    nrm[r] += __shfl_xor_sync(0xffffffffu, nrm[r], o);
            if ((t & 31) == 0) {
                #pragma unroll
                for (int r = 0; r < 16; ++r) {
                    int row = 16 * ty + r;
                    if (row < 64) rsA[row] = nrm[r];
                    else          rsB[row - 64] = nrm[r];
                }
            }
        }
    }

    if (t < 64)       { lmq[t] = __logf(fmaxf(mq[(size_t)b * 64 + t], 1e-8f)); la[t] = 0.f; }
    else if (t < 128) { lmr[t - 64] = __logf(fmaxf(mr[(size_t)b * 64 + (t - 64)], 1e-8f)); lb[t - 64] = 0.f; }
    __syncthreads();

    // ---- Gram -> C, lK (reads transposed fs); 4k x 4m per thread ------------
    {
        const int gx = t & 15, gy = t >> 4;
        unsigned long long g2[4][2];
        #pragma unroll
        for (int r = 0; r < 4; ++r) { g2[r][0] = 0ull; g2[r][1] = 0ull; }

        #pragma unroll 4
        for (int d = 0; d < 256; ++d) {
            const float4 xv = *(const float4*)&fs[d * FS_STRIDE + 4 * gy];
            const ulonglong2 yv = *(const ulonglong2*)&fs[d * FS_STRIDE + 64 + 4 * gx];
            float xr[4] = {xv.x, xv.y, xv.z, xv.w};
            #pragma unroll
            for (int r = 0; r < 4; ++r) {
                unsigned long long xp = pack2(xr[r], xr[r]);
                g2[r][0] = fma2(xp, yv.x, g2[r][0]);
                g2[r][1] = fma2(xp, yv.y, g2[r][1]);
            }
        }
        #pragma unroll
        for (int r = 0; r < 4; ++r) {
            int k = 4 * gy + r;
            float g[4];
            unpack2(g2[r][0], g[0], g[1]);
            unpack2(g2[r][1], g[2], g[3]);
            float nk = rsA[k];
            float lmqk = lmq[k];
            float4 c4;
            c4.x = sqrtf(fmaxf(nk + rsB[4 * gx + 0] - 2.f * g[0], 0.f));
            c4.y = sqrtf(fmaxf(nk + rsB[4 * gx + 1] - 2.f * g[1], 0.f));
            c4.z = sqrtf(fmaxf(nk + rsB[4 * gx + 2] - 2.f * g[2], 0.f));
            c4.w = sqrtf(fmaxf(nk + rsB[4 * gx + 3] - 2.f * g[3], 0.f));
            Cs[k * 65 + 4 * gx + 0] = c4.x;
            Cs[k * 65 + 4 * gx + 1] = c4.y;
            Cs[k * 65 + 4 * gx + 2] = c4.z;
            Cs[k * 65 + 4 * gx + 3] = c4.w;
            lKs[k * 65 + 4 * gx + 0] = -c4.x * 20.0f + lmqk + lmr[4 * gx + 0];
            lKs[k * 65 + 4 * gx + 1] = -c4.y * 20.0f + lmqk + lmr[4 * gx + 1];
            lKs[k * 65 + 4 * gx + 2] = -c4.z * 20.0f + lmqk + lmr[4 * gx + 2];
            lKs[k * 65 + 4 * gx + 3] = -c4.w * 20.0f + lmqk + lmr[4 * gx + 3];
            *(float4*)&out_C[((size_t)b * 64 + k) * 64 + 4 * gx] = c4;
        }
    }
    __syncthreads();

    // ---- Sinkhorn: 15 iterations, 4 threads per row/col ---------------------
    const int rk = t >> 2;
    const int q  = t & 3;
    for (int it = 0; it < NI_; ++it) {
        {   // la[k] = -lse_m(lK[k][m] + lb[m])
            float v[16], mx = -1e30f;
            #pragma unroll
            for (int j = 0; j < 16; ++j) {
                int m = q * 16 + j;
                v[j] = lKs[rk * 65 + m] + lb[m];
                mx = fmaxf(mx, v[j]);
            }
            mx = fmaxf(mx, __shfl_xor_sync(0xffffffffu, mx, 1));
            mx = fmaxf(mx, __shfl_xor_sync(0xffffffffu, mx, 2));
            float s = 0.f;
            #pragma unroll
            for (int j = 0; j < 16; ++j) s += __expf(v[j] - mx);
            s += __shfl_xor_sync(0xffffffffu, s, 1);
            s += __shfl_xor_sync(0xffffffffu, s, 2);
            if (q == 0) la[rk] = -(mx + __logf(s));
        }
        __syncthreads();
        {   // lb[m] = -lse_k(lK[k][m] + la[k])
            float v[16], mx = -1e30f;
            #pragma unroll
            for (int j = 0; j < 16; ++j) {
                int k = q * 16 + j;
                v[j] = lKs[k * 65 + rk] + la[k];
                mx = fmaxf(mx, v[j]);
            }
            mx = fmaxf(mx, __shfl_xor_sync(0xffffffffu, mx, 1));
            mx = fmaxf(mx, __shfl_xor_sync(0xffffffffu, mx, 2));
            float s = 0.f;
            #pragma unroll
            for (int j = 0; j < 16; ++j) s += __expf(v[j] - mx);
            s += __shfl_xor_sync(0xffffffffu, s, 1);
            s += __shfl_xor_sync(0xffffffffu, s, 2);
            if (q == 0) lb[rk] = -(mx + __logf(s));
        }
        __syncthreads();
    }

    // ---- T = exp(lK + la + lb) ---------------------------------------------
    {
        float lak = la[rk];
        #pragma unroll
        for (int j = 0; j < 16; ++j) {
            int m = q * 16 + j;
            Ts[rk * 65 + m] = __expf(lKs[rk * 65 + m] + lak + lb[m]);
        }
    }
    __syncthreads();

    // ---- power iterations ---------------------------------------------------
    for (int it = 0; it < MI_; ++it) {
        float s = 0.f;
        #pragma unroll
        for (int j = 0; j < 16; ++j) {
            int m = q * 16 + j;
            float v = Ts[rk * 65 + m];
            v *= v;
            Ts[rk * 65 + m] = v;
            s += v;
        }
        s += __shfl_xor_sync(0xffffffffu, s, 1);
        s += __shfl_xor_sync(0xffffffffu, s, 2);
        if (q == 0) rsA[rk] = s;
        __syncthreads();
        float dn = 1.f / (rsA[rk] + 1e-8f);
        #pragma unroll
        for (int j = 0; j < 16; ++j) Ts[rk * 65 + q * 16 + j] *= dn;
        __syncthreads();
        float cs = 0.f;
        #pragma unroll
        for (int j = 0; j < 16; ++j) cs += Ts[(q * 16 + j) * 65 + rk];
        cs += __shfl_xor_sync(0xffffffffu, cs, 1);
        cs += __shfl_xor_sync(0xffffffffu, cs, 2);
        if (q == 0) rsB[rk] = cs;
        __syncthreads();
        #pragma unroll
        for (int j = 0; j < 16; ++j) {
            int m = q * 16 + j;
            Ts[rk * 65 + m] /= (rsB[m] + 1e-8f);
        }
        __syncthreads();
    }

    // ---- c, sigmoid ---------------------------------------------------------
    {
        float s = 0.f;
        #pragma unroll
        for (int j = 0; j < 16; ++j) {
            int m = q * 16 + j;
            s += Ts[rk * 65 + m] * Cs[rk * 65 + m];
        }
        red[t] = s;
        __syncthreads();
        for (int off = 128; off > 0; off >>= 1) {
            if (t < off) red[t] += red[t + off];
            __syncthreads();
        }
        if (t == 0) {
            float c = red[0];
            out_c[b] = c;
            out_sig[b] = 1.f / (1.f + __expf(c));
        }
    }

    // ---- write T ------------------------------------------------------------
    {
        int row = t >> 2;
        int cb  = (t & 3) * 16;
        #pragma unroll
        for (int p = 0; p < 4; ++p) {
            float4 t4;
            t4.x = Ts[row * 65 + cb + 4 * p + 0];
            t4.y = Ts[row * 65 + cb + 4 * p + 1];
            t4.z = Ts[row * 65 + cb + 4 * p + 2];
            t4.w = Ts[row * 65 + cb + 4 * p + 3];
            *(float4*)&out_T[((size_t)b * 64 + row) * 64 + cb + 4 * p] = t4;
        }
    }
}

// ---------------------------------------------------------------------------
extern "C" void kernel_launch(void* const* d_in, const int* in_sizes, int n_in,
                              void* d_out, int out_size) {
    const float* sq = (const float*)d_in[0];
    const float* sr = (const float*)d_in[1];
    const float* mq = (const float*)d_in[2];
    const float* mr = (const float*)d_in[3];
    const float* W1 = (const float*)d_in[4];
    const float* b1 = (const float*)d_in[5];
    const float* W2 = (const float*)d_in[6];
    const float* b2 = (const float*)d_in[7];
    float* out = (float*)d_out;

    cudaFuncSetAttribute(fused_kernel, cudaFuncAttributeMaxDynamicSharedMemorySize, SMEM_BYTES);

    wprep_kernel<<<64, 256>>>(W1, W2);
    fused_kernel<<<B_, 256, SMEM_BYTES>>>(sq, sr, mq, mr, b1, b2, out);
}

// round 10
// speedup vs baseline: 1.3643x; 1.0949x over previous
#include <cuda_runtime.h>
#include <cstdint>

#define B_  2048
#define NI_ 15
#define MI_ 3

// ---------------------------------------------------------------------------
// smem layout (bytes):
//   [0, 135168): fsk = activation buffer, k-major [256 k][132 row] f32.
//     holds x, then h, then f (each overwrites the previous after a barrier).
//   [135168, 201728): 2 x (32k x 260e) f32 W chunk buffers.
//     phase 2 aliases: Cs@135168, lKs@151808, Ts@168448 (each 64x65 f32)
//   [201728, 207360): biases + small arrays
// ---------------------------------------------------------------------------
#define FS_STRIDE   132
#define WS0_OFF_F   (135168 / 4)
#define WS1_OFF_F   (168448 / 4)
#define CS_OFF_F    (135168 / 4)
#define LKS_OFF_F   (151808 / 4)
#define TS_OFF_F    (168448 / 4)
#define B1S_OFF_F   (201728 / 4)
#define B2S_OFF_F   (202752 / 4)
#define LA_OFF_F    (203776 / 4)
#define LB_OFF_F    (204032 / 4)
#define RSA_OFF_F   (204288 / 4)
#define RSB_OFF_F   (204544 / 4)
#define LMQ_OFF_F   (204800 / 4)
#define LMR_OFF_F   (205056 / 4)
#define RED_OFF_F   (205312 / 4)
#define SMEM_BYTES  207360

// W pre-transposed k-major: g_Wt[layer][k][e], 512 KB (L2-resident).
__device__ float g_Wt[2 * 256 * 256];

// ---------------------------------------------------------------------------
// tf32 split + mma helpers
// ---------------------------------------------------------------------------
__device__ __forceinline__ void tf32split(float x, uint32_t& hi, uint32_t& lo) {
    asm("cvt.rna.tf32.f32 %0, %1;" : "=r"(hi) : "f"(x));
    float d = x - __uint_as_float(hi);
    asm("cvt.rna.tf32.f32 %0, %1;" : "=r"(lo) : "f"(d));
}
__device__ __forceinline__ void mma8(float* d, const uint32_t* a, const uint32_t* b) {
    asm volatile(
        "mma.sync.aligned.m16n8k8.row.col.f32.tf32.tf32.f32 "
        "{%0,%1,%2,%3}, {%4,%5,%6,%7}, {%8,%9}, {%0,%1,%2,%3};"
        : "+f"(d[0]), "+f"(d[1]), "+f"(d[2]), "+f"(d[3])
        : "r"(a[0]), "r"(a[1]), "r"(a[2]), "r"(a[3]), "r"(b[0]), "r"(b[1]));
}

// packed f32x2 helpers (still used in the Gram phase)
__device__ __forceinline__ unsigned long long pack2(float lo, float hi) {
    unsigned long long r;
    asm("mov.b64 %0, {%1,%2};" : "=l"(r) : "f"(lo), "f"(hi));
    return r;
}
__device__ __forceinline__ void unpack2(unsigned long long v, float& lo, float& hi) {
    asm("mov.b64 {%0,%1}, %2;" : "=f"(lo), "=f"(hi) : "l"(v));
}
__device__ __forceinline__ unsigned long long fma2(unsigned long long a,
                                                   unsigned long long b,
                                                   unsigned long long c) {
    unsigned long long d;
    asm("fma.rn.f32x2 %0, %1, %2, %3;" : "=l"(d) : "l"(a), "l"(b), "l"(c));
    return d;
}

// ---------------------------------------------------------------------------
// W transpose prep: g_Wt[L][k][e] = W_L[e][k]
// ---------------------------------------------------------------------------
__global__ void wprep_kernel(const float* __restrict__ W1, const float* __restrict__ W2) {
    for (int i = blockIdx.x * 256 + threadIdx.x; i < 131072; i += gridDim.x * 256) {
        int L = i >> 16;
        int r = i & 65535;
        int k = r >> 8;
        int e = r & 255;
        g_Wt[i] = (L ? W2 : W1)[(size_t)e * 256 + k];
    }
}

// ---------------------------------------------------------------------------
// Fused kernel: one block per batch, 256 threads. MLP on tf32 mma.sync.
// ---------------------------------------------------------------------------
__global__ void __launch_bounds__(256, 1) fused_kernel(
    const float* __restrict__ sq, const float* __restrict__ sr,
    const float* __restrict__ mq, const float* __restrict__ mr,
    const float* __restrict__ b1, const float* __restrict__ b2,
    float* __restrict__ out)
{
    extern __shared__ float sm[];
    float* fsk = sm;                     // k-major activations [256][132]
    float* ws0 = sm + WS0_OFF_F;
    float* ws1 = sm + WS1_OFF_F;
    float* b1s = sm + B1S_OFF_F;
    float* b2s = sm + B2S_OFF_F;
    float* la  = sm + LA_OFF_F;
    float* lb  = sm + LB_OFF_F;
    float* rsA = sm + RSA_OFF_F;
    float* rsB = sm + RSB_OFF_F;
    float* lmq = sm + LMQ_OFF_F;
    float* lmr = sm + LMR_OFF_F;
    float* red = sm + RED_OFF_F;
    float* Cs  = sm + CS_OFF_F;
    float* lKs = sm + LKS_OFF_F;
    float* Ts  = sm + TS_OFF_F;

    const int t   = threadIdx.x;
    const int l   = t & 31;
    const int w   = t >> 5;
    const int mg  = w & 1;               // M group: rows 64*mg .. +63
    const int ng  = w >> 1;              // N group: cols 64*ng .. +63
    const int lg  = l >> 2;              // 0..7
    const int tig = l & 3;               // 0..3
    const int b   = blockIdx.x;

    float* out_sig = out;
    float* out_T   = out + B_;
    float* out_C   = out_T + (size_t)B_ * 64 * 64;
    float* out_c   = out_C + (size_t)B_ * 64 * 64;

    // ---- load x (coalesced) and transpose into fsk[k][row] ------------------
    {
        #pragma unroll
        for (int i = 0; i < 32; ++i) {
            int idx = t + i * 256;           // float4 index, 8192 total
            int row = idx >> 6;
            int d4  = (idx & 63) << 2;
            const float* src = (row < 64)
                ? sq + ((size_t)b * 64 + row) * 256
                : sr + ((size_t)b * 64 + (row - 64)) * 256;
            float4 v = *(const float4*)(src + d4);
            fsk[(d4 + 0) * FS_STRIDE + row] = v.x;
            fsk[(d4 + 1) * FS_STRIDE + row] = v.y;
            fsk[(d4 + 2) * FS_STRIDE + row] = v.z;
            fsk[(d4 + 3) * FS_STRIDE + row] = v.w;
        }
        b1s[t] = b1[t];
        b2s[t] = b2[t];
    }
    __syncthreads();

    // ---- 2-layer MLP via 3xTF32 mma.sync ------------------------------------
    // per warp: 4 m16 tiles x 8 n8 tiles, K=256 in 8 staged chunks of 32.
    float acc[4][8][4];

    for (int layer = 0; layer < 2; ++layer) {
        const float* Wt = g_Wt + layer * 65536;

        #pragma unroll
        for (int m = 0; m < 4; ++m)
            #pragma unroll
            for (int n = 0; n < 8; ++n)
                #pragma unroll
                for (int j = 0; j < 4; ++j) acc[m][n][j] = 0.f;

        // stage chunk 0 -> ws0
        #pragma unroll
        for (int i = 0; i < 8; ++i) {
            int idx = t + i * 256;
            int kk = idx >> 6, e4 = (idx & 63) << 2;
            *(float4*)&ws0[kk * 260 + e4] = *(const float4*)&Wt[kk * 256 + e4];
        }
        __syncthreads();

        for (int c = 0; c < 8; ++c) {
            float* wcur = (c & 1) ? ws1 : ws0;
            float* wnxt = (c & 1) ? ws0 : ws1;
            if (c < 7) {
                #pragma unroll
                for (int i = 0; i < 8; ++i) {
                    int idx = t + i * 256;
                    int kk = idx >> 6, e4 = (idx & 63) << 2;
                    *(float4*)&wnxt[kk * 260 + e4] =
                        *(const float4*)&Wt[(c + 1) * 8192 + kk * 256 + e4];
                }
            }
            #pragma unroll
            for (int ksl = 0; ksl < 4; ++ksl) {
                // B fragments (W), split on the fly, cached for all mtiles
                uint32_t whi[8][2], wlo[8][2];
                const float* wr0 = wcur + (ksl * 8 + tig) * 260 + ng * 64 + lg;
                const float* wr1 = wr0 + 4 * 260;
                #pragma unroll
                for (int n = 0; n < 8; ++n) {
                    tf32split(wr0[n * 8], whi[n][0], wlo[n][0]);
                    tf32split(wr1[n * 8], whi[n][1], wlo[n][1]);
                }
                const int kg = c * 32 + ksl * 8 + tig;
                #pragma unroll
                for (int m = 0; m < 4; ++m) {
                    const int r0 = mg * 64 + m * 16 + lg;
                    uint32_t ahi[4], alo[4];
                    tf32split(fsk[kg * FS_STRIDE + r0],           ahi[0], alo[0]);
                    tf32split(fsk[kg * FS_STRIDE + r0 + 8],       ahi[1], alo[1]);
                    tf32split(fsk[(kg + 4) * FS_STRIDE + r0],     ahi[2], alo[2]);
                    tf32split(fsk[(kg + 4) * FS_STRIDE + r0 + 8], ahi[3], alo[3]);
                    #pragma unroll
                    for (int n = 0; n < 8; ++n) {
                        mma8(acc[m][n], ahi, whi[n]);   // hi*hi
                        mma8(acc[m][n], alo, whi[n]);   // lo*hi
                        mma8(acc[m][n], ahi, wlo[n]);   // hi*lo
                    }
                }
            }
            __syncthreads();
        }

        // ---- epilogue: D-frags -> fsk k-major (conflict-free STS) -----------
        const float* bp = layer ? b2s : b1s;
        const bool relu = (layer == 0);
        #pragma unroll
        for (int m = 0; m < 4; ++m) {
            const int r0 = mg * 64 + m * 16 + lg;
            #pragma unroll
            for (int n = 0; n < 8; ++n) {
                const int cc = ng * 64 + n * 8 + 2 * tig;
                float bc0 = bp[cc], bc1 = bp[cc + 1];
                float v0 = acc[m][n][0] + bc0;
                float v1 = acc[m][n][1] + bc1;
                float v2 = acc[m][n][2] + bc0;
                float v3 = acc[m][n][3] + bc1;
                if (relu) {
                    v0 = fmaxf(v0, 0.f); v1 = fmaxf(v1, 0.f);
                    v2 = fmaxf(v2, 0.f); v3 = fmaxf(v3, 0.f);
                }
                fsk[cc * FS_STRIDE + r0]           = v0;
                fsk[(cc + 1) * FS_STRIDE + r0]     = v1;
                fsk[cc * FS_STRIDE + r0 + 8]       = v2;
                fsk[(cc + 1) * FS_STRIDE + r0 + 8] = v3;
            }
        }
        __syncthreads();
    }

    // ---- norms (2 threads per row over ALL 128 rows) + log marginals --------
    {
        int row = t >> 1, half = t & 1;      // row 0..127 at 256 threads
        float s = 0.f;
        #pragma unroll 8
        for (int i = 0; i < 128; ++i) {
            float v = fsk[(half * 128 + i) * FS_STRIDE + row];
            s += v * v;
        }
        s += __shfl_xor_sync(0xffffffffu, s, 1);
        if (half == 0) { if (row < 64) rsA[row] = s; else rsB[row - 64] = s; }
    }
    if (t < 64)       { lmq[t] = __logf(fmaxf(mq[(size_t)b * 64 + t], 1e-8f)); la[t] = 0.f; }
    else if (t < 128) { lmr[t - 64] = __logf(fmaxf(mr[(size_t)b * 64 + (t - 64)], 1e-8f)); lb[t - 64] = 0.f; }
    __syncthreads();

    // ---- Gram -> C, lK (reads fsk k-major); 4k x 4m per thread --------------
    {
        const int gx = t & 15, gy = t >> 4;
        unsigned long long g2[4][2];
        #pragma unroll
        for (int r = 0; r < 4; ++r) { g2[r][0] = 0ull; g2[r][1] = 0ull; }

        #pragma unroll 4
        for (int d = 0; d < 256; ++d) {
            const float4 xv = *(const float4*)&fsk[d * FS_STRIDE + 4 * gy];
            const ulonglong2 yv = *(const ulonglong2*)&fsk[d * FS_STRIDE + 64 + 4 * gx];
            float xr[4] = {xv.x, xv.y, xv.z, xv.w};
            #pragma unroll
            for (int r = 0; r < 4; ++r) {
                unsigned long long xp = pack2(xr[r], xr[r]);
                g2[r][0] = fma2(xp, yv.x, g2[r][0]);
                g2[r][1] = fma2(xp, yv.y, g2[r][1]);
            }
        }
        #pragma unroll
        for (int r = 0; r < 4; ++r) {
            int k = 4 * gy + r;
            float g[4];
            unpack2(g2[r][0], g[0], g[1]);
            unpack2(g2[r][1], g[2], g[3]);
            float nk = rsA[k];
            float lmqk = lmq[k];
            float4 c4;
            c4.x = sqrtf(fmaxf(nk + rsB[4 * gx + 0] - 2.f * g[0], 0.f));
            c4.y = sqrtf(fmaxf(nk + rsB[4 * gx + 1] - 2.f * g[1], 0.f));
            c4.z = sqrtf(fmaxf(nk + rsB[4 * gx + 2] - 2.f * g[2], 0.f));
            c4.w = sqrtf(fmaxf(nk + rsB[4 * gx + 3] - 2.f * g[3], 0.f));
            Cs[k * 65 + 4 * gx + 0] = c4.x;
            Cs[k * 65 + 4 * gx + 1] = c4.y;
            Cs[k * 65 + 4 * gx + 2] = c4.z;
            Cs[k * 65 + 4 * gx + 3] = c4.w;
            lKs[k * 65 + 4 * gx + 0] = -c4.x * 20.0f + lmqk + lmr[4 * gx + 0];
            lKs[k * 65 + 4 * gx + 1] = -c4.y * 20.0f + lmqk + lmr[4 * gx + 1];
            lKs[k * 65 + 4 * gx + 2] = -c4.z * 20.0f + lmqk + lmr[4 * gx + 2];
            lKs[k * 65 + 4 * gx + 3] = -c4.w * 20.0f + lmqk + lmr[4 * gx + 3];
            *(float4*)&out_C[((size_t)b * 64 + k) * 64 + 4 * gx] = c4;
        }
    }
    __syncthreads();

    // ---- Sinkhorn: 15 iterations, 4 threads per row/col ---------------------
    const int rk = t >> 2;
    const int q  = t & 3;
    for (int it = 0; it < NI_; ++it) {
        {   // la[k] = -lse_m(lK[k][m] + lb[m])
            float v[16], mx = -1e30f;
            #pragma unroll
            for (int j = 0; j < 16; ++j) {
                int m = q * 16 + j;
                v[j] = lKs[rk * 65 + m] + lb[m];
                mx = fmaxf(mx, v[j]);
            }
            mx = fmaxf(mx, __shfl_xor_sync(0xffffffffu, mx, 1));
            mx = fmaxf(mx, __shfl_xor_sync(0xffffffffu, mx, 2));
            float s = 0.f;
            #pragma unroll
            for (int j = 0; j < 16; ++j) s += __expf(v[j] - mx);
            s += __shfl_xor_sync(0xffffffffu, s, 1);
            s += __shfl_xor_sync(0xffffffffu, s, 2);
            if (q == 0) la[rk] = -(mx + __logf(s));
        }
        __syncthreads();
        {   // lb[m] = -lse_k(lK[k][m] + la[k])
            float v[16], mx = -1e30f;
            #pragma unroll
            for (int j = 0; j < 16; ++j) {
                int k = q * 16 + j;
                v[j] = lKs[k * 65 + rk] + la[k];
                mx = fmaxf(mx, v[j]);
            }
            mx = fmaxf(mx, __shfl_xor_sync(0xffffffffu, mx, 1));
            mx = fmaxf(mx, __shfl_xor_sync(0xffffffffu, mx, 2));
            float s = 0.f;
            #pragma unroll
            for (int j = 0; j < 16; ++j) s += __expf(v[j] - mx);
            s += __shfl_xor_sync(0xffffffffu, s, 1);
            s += __shfl_xor_sync(0xffffffffu, s, 2);
            if (q == 0) lb[rk] = -(mx + __logf(s));
        }
        __syncthreads();
    }

    // ---- T = exp(lK + la + lb) ---------------------------------------------
    {
        float lak = la[rk];
        #pragma unroll
        for (int j = 0; j < 16; ++j) {
            int m = q * 16 + j;
            Ts[rk * 65 + m] = __expf(lKs[rk * 65 + m] + lak + lb[m]);
        }
    }
    __syncthreads();

    // ---- power iterations ---------------------------------------------------
    for (int it = 0; it < MI_; ++it) {
        float s = 0.f;
        #pragma unroll
        for (int j = 0; j < 16; ++j) {
            int m = q * 16 + j;
            float v = Ts[rk * 65 + m];
            v *= v;
            Ts[rk * 65 + m] = v;
            s += v;
        }
        s += __shfl_xor_sync(0xffffffffu, s, 1);
        s += __shfl_xor_sync(0xffffffffu, s, 2);
        if (q == 0) rsA[rk] = s;
        __syncthreads();
        float dn = 1.f / (rsA[rk] + 1e-8f);
        #pragma unroll
        for (int j = 0; j < 16; ++j) Ts[rk * 65 + q * 16 + j] *= dn;
        __syncthreads();
        float cs = 0.f;
        #pragma unroll
        for (int j = 0; j < 16; ++j) cs += Ts[(q * 16 + j) * 65 + rk];
        cs += __shfl_xor_sync(0xffffffffu, cs, 1);
        cs += __shfl_xor_sync(0xffffffffu, cs, 2);
        if (q == 0) rsB[rk] = cs;
        __syncthreads();
        #pragma unroll
        for (int j = 0; j < 16; ++j) {
            int m = q * 16 + j;
            Ts[rk * 65 + m] /= (rsB[m] + 1e-8f);
        }
        __syncthreads();
    }

    // ---- c, sigmoid ---------------------------------------------------------
    {
        float s = 0.f;
        #pragma unroll
        for (int j = 0; j < 16; ++j) {
            int m = q * 16 + j;
            s += Ts[rk * 65 + m] * Cs[rk * 65 + m];
        }
        red[t] = s;
        __syncthreads();
        for (int off = 128; off > 0; off >>= 1) {
            if (t < off) red[t] += red[t + off];
            __syncthreads();
        }
        if (t == 0) {
            float c = red[0];
            out_c[b] = c;
            out_sig[b] = 1.f / (1.f + __expf(c));
        }
    }

    // ---- write T ------------------------------------------------------------
    {
        int row = t >> 2;
        int cb  = (t & 3) * 16;
        #pragma unroll
        for (int p = 0; p < 4; ++p) {
            float4 t4;
            t4.x = Ts[row * 65 + cb + 4 * p + 0];
            t4.y = Ts[row * 65 + cb + 4 * p + 1];
            t4.z = Ts[row * 65 + cb + 4 * p + 2];
            t4.w = Ts[row * 65 + cb + 4 * p + 3];
            *(float4*)&out_T[((size_t)b * 64 + row) * 64 + cb + 4 * p] = t4;
        }
    }
}

// ---------------------------------------------------------------------------
extern "C" void kernel_launch(void* const* d_in, const int* in_sizes, int n_in,
                              void* d_out, int out_size) {
    const float* sq = (const float*)d_in[0];
    const float* sr = (const float*)d_in[1];
    const float* mq = (const float*)d_in[2];
    const float* mr = (const float*)d_in[3];
    const float* W1 = (const float*)d_in[4];
    const float* b1 = (const float*)d_in[5];
    const float* W2 = (const float*)d_in[6];
    const float* b2 = (const float*)d_in[7];
    float* out = (float*)d_out;

    cudaFuncSetAttribute(fused_kernel, cudaFuncAttributeMaxDynamicSharedMemorySize, SMEM_BYTES);

    wprep_kernel<<<64, 256>>>(W1, W2);
    fused_kernel<<<B_, 256, SMEM_BYTES>>>(sq, sr, mq, mr, b1, b2, out);
}